// round 13
// baseline (speedup 1.0000x reference)
#include <cuda_runtime.h>
#include <cuda_bf16.h>
#include <cstdint>

// SudokuDigitsDoubles — exact boolean reduction ("naked pairs" row elimination).
//
// Round 13: 4-slot cp.async.bulk ring at PPB=8, lookahead 2, persistent CTAs.
// Fixes the R9/R11/R12 serialization where each prefetch's wait_group.read 0
// chained the next load behind the store issued nanoseconds earlier: with 4
// slots, the prefetch of tile k+2 reuses the slot of tile k-2 (store committed
// two iterations ago), so the guard is wait_group.read 1 — only the OLDER
// pending store must have drained smem. Compute: 72 row leaders read their 81
// floats straight from the smem tile, edit in place only if the row has an
// active naked pair (~0.5% of rows).

static constexpr int PUZ = 729;                   // floats per puzzle
static constexpr int PPB = 8;                     // puzzles per tile
static constexpr int NF  = PPB * PUZ;             // 5832 floats per tile
static constexpr unsigned TILE_BYTES = NF * 4;    // 23328
static constexpr int NBUF = 4;
static constexpr int LOOKAHEAD = 2;
static constexpr int THREADS = 256;
static constexpr int GRID_CTAS = 296;             // 2 per SM * 148 SMs
static constexpr unsigned SMEM_BYTES = NBUF * TILE_BYTES + 256;

__device__ __forceinline__ unsigned smem_u32(const void* p) {
    unsigned a;
    asm("{ .reg .u64 t; cvta.to.shared.u64 t, %1; cvt.u32.u64 %0, t; }"
        : "=r"(a) : "l"(p));
    return a;
}

__device__ __forceinline__ void mbar_wait(unsigned bar, unsigned parity) {
    unsigned done;
    do {
        asm volatile(
            "{\n\t.reg .pred p;\n\t"
            "mbarrier.try_wait.parity.acquire.cta.shared::cta.b64 p, [%1], %2;\n\t"
            "selp.b32 %0, 1, 0, p;\n\t}"
            : "=r"(done) : "r"(bar), "r"(parity) : "memory");
    } while (!done);
}

__device__ __forceinline__ void bulk_load(unsigned dst, const float* src,
                                          unsigned bar, unsigned long long pol) {
    asm volatile("mbarrier.arrive.expect_tx.shared.b64 _, [%0], %1;"
                 :: "r"(bar), "r"(TILE_BYTES) : "memory");
    asm volatile(
        "cp.async.bulk.shared::cluster.global.mbarrier::complete_tx::bytes"
        ".L2::cache_hint [%0], [%1], %2, [%3], %4;"
        :: "r"(dst), "l"(src), "r"(TILE_BYTES), "r"(bar), "l"(pol) : "memory");
}

__global__ __launch_bounds__(THREADS, 2)
void sudoku_doubles_kernel(const float* __restrict__ in,
                           float* __restrict__ out,
                           int nPuz, int nTiles)
{
    extern __shared__ char smraw[];
    uintptr_t base = ((uintptr_t)smraw + 127) & ~(uintptr_t)127;
    float* bufp = reinterpret_cast<float*>(base);
    unsigned long long* mbar =
        reinterpret_cast<unsigned long long*>(bufp + NBUF * NF);

    const unsigned tid = threadIdx.x;
    unsigned sBar[NBUF], sBuf[NBUF];
    #pragma unroll
    for (int i = 0; i < NBUF; i++) {
        sBar[i] = smem_u32(&mbar[i]);
        sBuf[i] = smem_u32(bufp + i * NF);
    }

    // both streams are touch-once: keep L2 as a pure bandwidth filter
    unsigned long long polStream;
    asm("createpolicy.fractional.L2::evict_first.b64 %0, 1.0;" : "=l"(polStream));

    if (tid == 0) {
        #pragma unroll
        for (int i = 0; i < NBUF; i++)
            asm volatile("mbarrier.init.shared.b64 [%0], 1;" :: "r"(sBar[i]) : "memory");
    }
    __syncthreads();

    // ---- prologue: LOOKAHEAD loads into slots 0..LOOKAHEAD-1 ----
    if (tid == 0) {
        #pragma unroll
        for (int q = 0; q < LOOKAHEAD; q++) {
            const int t = blockIdx.x + q * gridDim.x;
            if (t < nTiles) {
                const int tb = t * PPB;
                if (tb + PPB <= nPuz)
                    bulk_load(sBuf[q], in + (size_t)tb * PUZ, sBar[q], polStream);
            }
        }
    }

    int k = 0;
    for (int tile = blockIdx.x; tile < nTiles; tile += gridDim.x, k++) {
        const int s = k & (NBUF - 1);

        // ---- prefetch tile k+LOOKAHEAD into slot (k+LOOKAHEAD)&3 ----
        {
            const int pt = tile + LOOKAHEAD * gridDim.x;
            if (tid == 0 && pt < nTiles) {
                const int ptb = pt * PPB;
                if (ptb + PPB <= nPuz) {
                    // target slot last stored 2 iterations ago: only the OLDER
                    // pending store group must have finished reading smem
                    asm volatile("cp.async.bulk.wait_group.read 1;" ::: "memory");
                    const int ps = (k + LOOKAHEAD) & (NBUF - 1);
                    bulk_load(sBuf[ps], in + (size_t)ptb * PUZ, sBar[ps], polStream);
                }
            }
        }

        const int tileBase = tile * PPB;
        if (tileBase + PPB <= nPuz) {
            // slot s is used every NBUF tiles; parity = use-count & 1
            mbar_wait(sBar[s], (unsigned)((k >> 2) & 1));

            // ---- 72 row leaders: logic straight off the smem tile ----
            if (tid < PPB * 9) {
                const int pl = tid / 9;
                const int r  = tid - 9 * pl;
                float* tilebuf = bufp + s * NF;
                const unsigned* rowp =
                    reinterpret_cast<const unsigned*>(tilebuf) + pl * PUZ + r * 9;

                int m[9], pv[9];
                #pragma unroll
                for (int c = 0; c < 9; c++) {
                    unsigned mm = 0;
                    #pragma unroll
                    for (int d = 0; d < 9; d++)
                        mm |= ((rowp[d * 81 + c] >> 23) & 1u) << d;  // 1.0f vs 0.0f
                    m[c]  = (int)mm;
                    pv[c] = (__popc(mm) == 2) ? m[c] : 0;
                }
                int act = 0, tor = 0;
                #pragma unroll
                for (int j = 0; j < 9; j++) {
                    int cc = 0;
                    #pragma unroll
                    for (int kk = 0; kk < 9; kk++)
                        cc += (pv[kk] == pv[j]) ? 1 : 0;
                    const bool a = (pv[j] != 0) & (cc == 2);
                    act |= a ? (1 << j) : 0;
                    tor |= a ? pv[j] : 0;
                }
                if (act) {   // rare: ~0.5% of rows
                    float* o = tilebuf + pl * PUZ + r * 9;
                    #pragma unroll
                    for (int c = 0; c < 9; c++) {
                        int erase;
                        if ((act >> c) & 1) {
                            erase = 0;
                            #pragma unroll
                            for (int j = 0; j < 9; j++)
                                if (((act >> j) & 1) && pv[j] != pv[c])
                                    erase |= pv[j];
                        } else {
                            erase = tor;
                        }
                        const int keep = m[c] & ~erase;
                        #pragma unroll
                        for (int d = 0; d < 9; d++)
                            o[d * 81 + c] = ((keep >> d) & 1) ? 1.0f : 0.0f;
                    }
                }
            }
            __syncthreads();

            // ---- bulk store this tile (one group per iteration) ----
            if (tid == 0) {
                asm volatile("fence.proxy.async.shared::cta;" ::: "memory");
                asm volatile(
                    "cp.async.bulk.global.shared::cta.bulk_group"
                    ".L2::cache_hint [%0], [%1], %2, %3;"
                    :: "l"(out + (size_t)tileBase * PUZ), "r"(sBuf[s]),
                       "r"(TILE_BYTES), "l"(polStream) : "memory");
                asm volatile("cp.async.bulk.commit_group;" ::: "memory");
            }
        } else {
            // ---- partial tail tile: direct scalar path (unused for B=32768) ----
            const int puzCount = nPuz - tileBase;
            if (puzCount > 0 && tid < (unsigned)(puzCount * 9)) {
                const int pl = tid / 9;
                const int r  = tid - 9 * pl;
                const float* gi = in  + (size_t)(tileBase + pl) * PUZ + r * 9;
                float*       go = out + (size_t)(tileBase + pl) * PUZ + r * 9;
                int m[9], pv[9];
                #pragma unroll
                for (int c = 0; c < 9; c++) {
                    unsigned mm = 0;
                    #pragma unroll
                    for (int d = 0; d < 9; d++)
                        mm |= ((__float_as_uint(gi[d * 81 + c]) >> 23) & 1u) << d;
                    m[c]  = (int)mm;
                    pv[c] = (__popc(mm) == 2) ? m[c] : 0;
                }
                int act = 0, tor = 0;
                #pragma unroll
                for (int j = 0; j < 9; j++) {
                    int cc = 0;
                    #pragma unroll
                    for (int kk = 0; kk < 9; kk++)
                        cc += (pv[kk] == pv[j]) ? 1 : 0;
                    const bool a = (pv[j] != 0) & (cc == 2);
                    act |= a ? (1 << j) : 0;
                    tor |= a ? pv[j] : 0;
                }
                #pragma unroll
                for (int c = 0; c < 9; c++) {
                    int erase;
                    if ((act >> c) & 1) {
                        erase = 0;
                        #pragma unroll
                        for (int j = 0; j < 9; j++)
                            if (((act >> j) & 1) && pv[j] != pv[c])
                                erase |= pv[j];
                    } else {
                        erase = tor;
                    }
                    const int keep = m[c] & ~erase;
                    #pragma unroll
                    for (int d = 0; d < 9; d++)
                        go[d * 81 + c] = ((keep >> d) & 1) ? 1.0f : 0.0f;
                }
            }
        }
    }

    // drain: all stores must finish reading smem before the CTA exits
    if (tid == 0)
        asm volatile("cp.async.bulk.wait_group.read 0;" ::: "memory");
}

extern "C" void kernel_launch(void* const* d_in, const int* in_sizes, int n_in,
                              void* d_out, int out_size)
{
    const float* mask = (const float*)d_in[0];
    float* out = (float*)d_out;
    const int nPuz = in_sizes[0] / PUZ;                 // 32768
    const int nTiles = (nPuz + PPB - 1) / PPB;          // 4096
    const int grid = (nTiles < GRID_CTAS) ? nTiles : GRID_CTAS;

    // opt-in to >48KB dynamic smem (idempotent attribute set; capture-safe)
    cudaFuncSetAttribute(sudoku_doubles_kernel,
                         cudaFuncAttributeMaxDynamicSharedMemorySize, SMEM_BYTES);

    sudoku_doubles_kernel<<<grid, THREADS, SMEM_BYTES>>>(mask, out, nPuz, nTiles);
}

// round 14
// speedup vs baseline: 1.0482x; 1.0482x over previous
#include <cuda_runtime.h>
#include <cuda_bf16.h>
#include <cstdint>

// SudokuDigitsDoubles — exact boolean reduction ("naked pairs" row elimination).
//
// Round 14: the R11 winner (persistent CTAs, double-buffered cp.async.bulk,
// L2 hints, 4 CTAs/SM) with THREADS=128 instead of 256. Steady-state work is
// tid0 (bulk ops) + tids 0..71 (row leaders); the upper 184 threads of R11
// only widened every barrier/mbarrier wait. Same grid (592), same smem,
// same memory behavior — half the barrier width and idle-warp pressure.

static constexpr int PUZ = 729;                  // floats per puzzle
static constexpr int PPB = 8;                    // puzzles per tile
static constexpr int NF  = PPB * PUZ;            // 5832 floats per tile
static constexpr unsigned TILE_BYTES = NF * 4;   // 23328
static constexpr int THREADS = 128;
static constexpr int GRID_CTAS = 592;            // 4 per SM * 148 SMs

__device__ __forceinline__ unsigned smem_u32(const void* p) {
    unsigned a;
    asm("{ .reg .u64 t; cvta.to.shared.u64 t, %1; cvt.u32.u64 %0, t; }"
        : "=r"(a) : "l"(p));
    return a;
}

__device__ __forceinline__ void mbar_wait(unsigned bar, unsigned parity) {
    unsigned done;
    do {
        asm volatile(
            "{\n\t.reg .pred p;\n\t"
            "mbarrier.try_wait.parity.acquire.cta.shared::cta.b64 p, [%1], %2;\n\t"
            "selp.b32 %0, 1, 0, p;\n\t}"
            : "=r"(done) : "r"(bar), "r"(parity) : "memory");
    } while (!done);
}

__device__ __forceinline__ void bulk_load_resident(unsigned dst, const float* src,
                                                   unsigned bar,
                                                   unsigned long long pol) {
    asm volatile("mbarrier.arrive.expect_tx.shared.b64 _, [%0], %1;"
                 :: "r"(bar), "r"(TILE_BYTES) : "memory");
    asm volatile(
        "cp.async.bulk.shared::cluster.global.mbarrier::complete_tx::bytes"
        ".L2::cache_hint [%0], [%1], %2, [%3], %4;"
        :: "r"(dst), "l"(src), "r"(TILE_BYTES), "r"(bar), "l"(pol) : "memory");
}

__global__ __launch_bounds__(THREADS, 4)
void sudoku_doubles_kernel(const float* __restrict__ in,
                           float* __restrict__ out,
                           int nPuz, int nTiles)
{
    __shared__ alignas(128) float buf[2][NF];
    __shared__ alignas(8) unsigned long long mbar[2];

    const unsigned tid = threadIdx.x;
    const unsigned sBar[2] = { smem_u32(&mbar[0]), smem_u32(&mbar[1]) };
    const unsigned sBuf[2] = { smem_u32(buf[0]),   smem_u32(buf[1])   };

    unsigned long long polLast, polFirst;
    asm("createpolicy.fractional.L2::evict_last.b64 %0, 1.0;"  : "=l"(polLast));
    asm("createpolicy.fractional.L2::evict_first.b64 %0, 1.0;" : "=l"(polFirst));

    if (tid == 0) {
        asm volatile("mbarrier.init.shared.b64 [%0], 1;" :: "r"(sBar[0]) : "memory");
        asm volatile("mbarrier.init.shared.b64 [%0], 1;" :: "r"(sBar[1]) : "memory");
    }
    __syncthreads();

    int ph[2] = {0, 0};
    int b = 0;

    // prologue: first tile's load
    {
        const int tile = blockIdx.x;
        if (tid == 0 && tile < nTiles) {
            const int tb = tile * PPB;
            if (tb + PPB <= nPuz)
                bulk_load_resident(sBuf[0], in + (size_t)tb * PUZ, sBar[0], polLast);
        }
    }

    for (int tile = blockIdx.x; tile < nTiles; tile += gridDim.x, b ^= 1) {
        const int tileBase = tile * PPB;
        const bool full = (tileBase + PPB <= nPuz);

        // ---- prefetch next tile into the other buffer ----
        const int nextTile = tile + gridDim.x;
        if (tid == 0 && nextTile < nTiles) {
            const int ntb = nextTile * PPB;
            if (ntb + PPB <= nPuz) {
                asm volatile("cp.async.bulk.wait_group.read 0;" ::: "memory");
                bulk_load_resident(sBuf[b ^ 1], in + (size_t)ntb * PUZ,
                                   sBar[b ^ 1], polLast);
            }
        }

        if (full) {
            mbar_wait(sBar[b], (unsigned)ph[b]);
            ph[b] ^= 1;

            // ---- 72 row leaders: logic directly on the smem tile ----
            if (tid < PPB * 9) {
                const int pl = tid / 9;
                const int r  = tid - 9 * pl;
                const unsigned* rowp =
                    reinterpret_cast<const unsigned*>(buf[b]) + pl * PUZ + r * 9;

                int m[9], pv[9];
                #pragma unroll
                for (int c = 0; c < 9; c++) {
                    unsigned mm = 0;
                    #pragma unroll
                    for (int d = 0; d < 9; d++)
                        mm |= ((rowp[d * 81 + c] >> 23) & 1u) << d;  // 1.0f vs 0.0f
                    m[c]  = (int)mm;
                    pv[c] = (__popc(mm) == 2) ? m[c] : 0;
                }
                int act = 0, tor = 0;
                #pragma unroll
                for (int j = 0; j < 9; j++) {
                    int cc = 0;
                    #pragma unroll
                    for (int k = 0; k < 9; k++)
                        cc += (pv[k] == pv[j]) ? 1 : 0;
                    const bool a = (pv[j] != 0) & (cc == 2);
                    act |= a ? (1 << j) : 0;
                    tor |= a ? pv[j] : 0;
                }
                if (act) {   // rare: ~0.5% of rows
                    float* o = buf[b] + pl * PUZ + r * 9;
                    #pragma unroll
                    for (int c = 0; c < 9; c++) {
                        int erase;
                        if ((act >> c) & 1) {
                            erase = 0;
                            #pragma unroll
                            for (int j = 0; j < 9; j++)
                                if (((act >> j) & 1) && pv[j] != pv[c])
                                    erase |= pv[j];
                        } else {
                            erase = tor;
                        }
                        const int keep = m[c] & ~erase;
                        #pragma unroll
                        for (int d = 0; d < 9; d++)
                            o[d * 81 + c] = ((keep >> d) & 1) ? 1.0f : 0.0f;
                    }
                }
            }
            __syncthreads();

            // ---- bulk store this tile (streaming, evict_first) ----
            if (tid == 0) {
                asm volatile("fence.proxy.async.shared::cta;" ::: "memory");
                asm volatile(
                    "cp.async.bulk.global.shared::cta.bulk_group"
                    ".L2::cache_hint [%0], [%1], %2, %3;"
                    :: "l"(out + (size_t)tileBase * PUZ), "r"(sBuf[b]),
                       "r"(TILE_BYTES), "l"(polFirst) : "memory");
                asm volatile("cp.async.bulk.commit_group;" ::: "memory");
            }
        } else {
            // ---- partial tail tile: direct scalar path (unused for B=32768) ----
            const int puzCount = nPuz - tileBase;
            if (puzCount > 0 && tid < (unsigned)(puzCount * 9)) {
                const int pl = tid / 9;
                const int r  = tid - 9 * pl;
                const float* gi = in  + (size_t)(tileBase + pl) * PUZ + r * 9;
                float*       go = out + (size_t)(tileBase + pl) * PUZ + r * 9;
                int m[9], pv[9];
                #pragma unroll
                for (int c = 0; c < 9; c++) {
                    unsigned mm = 0;
                    #pragma unroll
                    for (int d = 0; d < 9; d++)
                        mm |= ((__float_as_uint(gi[d * 81 + c]) >> 23) & 1u) << d;
                    m[c]  = (int)mm;
                    pv[c] = (__popc(mm) == 2) ? m[c] : 0;
                }
                int act = 0, tor = 0;
                #pragma unroll
                for (int j = 0; j < 9; j++) {
                    int cc = 0;
                    #pragma unroll
                    for (int k = 0; k < 9; k++)
                        cc += (pv[k] == pv[j]) ? 1 : 0;
                    const bool a = (pv[j] != 0) & (cc == 2);
                    act |= a ? (1 << j) : 0;
                    tor |= a ? pv[j] : 0;
                }
                #pragma unroll
                for (int c = 0; c < 9; c++) {
                    int erase;
                    if ((act >> c) & 1) {
                        erase = 0;
                        #pragma unroll
                        for (int j = 0; j < 9; j++)
                            if (((act >> j) & 1) && pv[j] != pv[c])
                                erase |= pv[j];
                    } else {
                        erase = tor;
                    }
                    const int keep = m[c] & ~erase;
                    #pragma unroll
                    for (int d = 0; d < 9; d++)
                        go[d * 81 + c] = ((keep >> d) & 1) ? 1.0f : 0.0f;
                }
            }
        }
    }

    // drain: last store must finish reading smem before the CTA exits
    if (tid == 0)
        asm volatile("cp.async.bulk.wait_group.read 0;" ::: "memory");
}

extern "C" void kernel_launch(void* const* d_in, const int* in_sizes, int n_in,
                              void* d_out, int out_size)
{
    const float* mask = (const float*)d_in[0];
    float* out = (float*)d_out;
    const int nPuz = in_sizes[0] / PUZ;                 // 32768
    const int nTiles = (nPuz + PPB - 1) / PPB;          // 4096
    const int grid = (nTiles < GRID_CTAS) ? nTiles : GRID_CTAS;
    sudoku_doubles_kernel<<<grid, THREADS>>>(mask, out, nPuz, nTiles);
}